// round 16
// baseline (speedup 1.0000x reference)
#include <cuda_runtime.h>
#include <math.h>

// Problem shapes (fixed)
#define NB 512
#define NW 1024
#define NL 64
#define NJ 8
#define NI 32
#define NO 128
#define NK 2048   // L*I
#define NSPLIT 3  // w-splits of kA: chunks {3,3,2} x 128 w

// ---------------- device scratch (no allocations allowed) -------------------
__device__ float g_best[NJ * NB * NL];       // best[j][b][l]        (1 MB)
__device__ float g_cv  [NB * NI];            // body contribution
__device__ float g_cvp [4 * NJ * NB * NI];   // slot partials [kq][j][b][i]
__device__ float g_conf[NB];                 // exp(-total_mq)
__device__ float p_Z   [NSPLIT * NB * NJ];   // partial Z   [zi][b][j]
__device__ float p_Q   [NSPLIT * NB * NJ];   // partial sum e*s
__device__ float p_C   [NSPLIT * NB * NJ];   // per-split exp offset
__device__ float p_best[NSPLIT * NJ * NB * NL];  // raw sum e*x (3 MB)

// ---------------- packed f32x2 helpers (Blackwell FFMA2) --------------------
static __device__ __forceinline__ unsigned long long pk2(float x, float y) {
    unsigned long long r;
    asm("mov.b64 %0, {%1,%2};" : "=l"(r) : "f"(x), "f"(y));
    return r;
}
static __device__ __forceinline__ void fma2(unsigned long long& d,
                                            unsigned long long a,
                                            unsigned long long b) {
    asm("fma.rn.f32x2 %0, %1, %2, %0;" : "+l"(d) : "l"(a), "l"(b));
}
static __device__ __forceinline__ float2 up2(unsigned long long v) {
    float2 r;
    asm("mov.b64 {%0,%1}, %2;" : "=f"(r.x), "=f"(r.y) : "l"(v));
    return r;
}

// =============================================================================
// Kernel A1: partial scores/softmax/best for one (b, w-split).
// grid = (512 b, 3 zi), 128 threads. zi 0/1: chunks 0-2/3-5; zi 2: chunks 6-7.
// =============================================================================
#define CW     128
#define A_COEF 0
#define A_TILE 1024
#define A_SCB  (A_TILE + 128*65)      // 9344
#define A_AS   (A_SCB + 1024)         // 10368
#define A_CS   (A_AS + 8)
#define A_ZW   (A_CS + 8)             // 4 warps x 4
#define A_QW   (A_ZW + 16)
#define A_SMEM_FLOATS (A_QW + 16)     // 10408

extern "C" __global__ void __launch_bounds__(128, 5)
kA1(const float* __restrict__ wm, const float* __restrict__ constants,
    const float* __restrict__ gammas)
{
    extern __shared__ float sm[];
    unsigned long long* coefT = (unsigned long long*)(sm + A_COEF); // [l*8+j]
    float* tile = sm + A_TILE;
    float* scb  = sm + A_SCB;
    float* As   = sm + A_AS;
    float* Cs   = sm + A_CS;
    float* zw   = sm + A_ZW;
    float* qw   = sm + A_QW;

    const int t    = threadIdx.x;
    const int b    = blockIdx.x;
    const int zi   = blockIdx.y;
    const int lane = t & 31;
    const int wid  = t >> 5;          // 0..3
    const int wp   = t & 63;          // score: w in {wp, wp+64}
    const int jh   = t >> 6;          // score: j in {4jh..4jh+3}

    const int s0  = zi * 3;                    // first chunk
    const int nch = (zi < 2) ? 3 : 2;          // chunk count

    // ---- Phase 0: coefficients (scratch in tile) ----
    for (int e = t; e < NJ * NL; e += 128) {
        float g = gammas[e];
        g = fminf(fmaxf(g, 0.f), 1.f);
        float w1 = 1.f - g;
        float c  = constants[e];
        int j = e >> 6, l = e & 63;
        coefT[l * 8 + j] = pk2(-2.f * w1 * c, w1);
        tile[e] = w1 * c * c;
    }
    __syncthreads();
    if (t < 8) {
        float a = 0.f;
        for (int l = 0; l < NL; l++) a += tile[t * 64 + l];
        As[t] = a;
    }
    __syncthreads();

    float Areg[4];
#pragma unroll
    for (int k = 0; k < 4; k++) Areg[k] = As[4 * jh + k];
    const ulonglong2* cT = (const ulonglong2*)coefT;   // [l*4 + 2jh (+1)]
    const float* wmb = wm + (size_t)b * (NW * NL);

    unsigned long long accP[2][4];        // best accum: [x-half][(j,j+1) pair]
#pragma unroll
    for (int h = 0; h < 2; h++)
#pragma unroll
        for (int p = 0; p < 4; p++) accP[h][p] = pk2(0.f, 0.f);
    float zp[4] = {0.f, 0.f, 0.f, 0.f};
    float qp[4] = {0.f, 0.f, 0.f, 0.f};
    float Cr[4] = {0.f, 0.f, 0.f, 0.f};   // exp offsets (set @ first chunk)

    for (int ch = s0; ch < s0 + nch; ch++) {
        __syncthreads();
        // ---- stage 128-w chunk (128 threads, 16 float4 each) ----
        const float4* src = (const float4*)(wmb + ch * CW * 64);
#pragma unroll
        for (int qq = 0; qq < 16; qq++) {
            int f = t + 128 * qq;            // 0..2047 float4s
            int row = f >> 4, c4 = f & 15;
            float4 v = src[f];
            float* dst = tile + row * 65 + c4 * 4;
            dst[0] = v.x; dst[1] = v.y; dst[2] = v.z; dst[3] = v.w;
        }
        __syncthreads();

        // ---- scores: w in {wp, wp+64}, j = 4jh..4jh+3 ----
        unsigned long long s00 = pk2(Areg[0], 0.f);
        unsigned long long s01 = pk2(Areg[1], 0.f);
        unsigned long long s02 = pk2(Areg[2], 0.f);
        unsigned long long s03 = pk2(Areg[3], 0.f);
        unsigned long long s10 = s00, s11 = s01, s12 = s02, s13 = s03;
        const float* r0 = tile + wp * 65;
        const float* r1 = tile + (wp + 64) * 65;
#pragma unroll 16
        for (int l = 0; l < 64; l++) {
            float x0 = r0[l], x1 = r1[l];
            unsigned long long a0 = pk2(x0, x0 * x0);
            unsigned long long a1 = pk2(x1, x1 * x1);
            ulonglong2 ccA = cT[l * 4 + 2 * jh];
            ulonglong2 ccB = cT[l * 4 + 2 * jh + 1];
            fma2(s00, a0, ccA.x); fma2(s01, a0, ccA.y);
            fma2(s02, a0, ccB.x); fma2(s03, a0, ccB.y);
            fma2(s10, a1, ccA.x); fma2(s11, a1, ccA.y);
            fma2(s12, a1, ccB.x); fma2(s13, a1, ccB.y);
        }
        float sv0[4], sv1[4];
        { float2 p = up2(s00); sv0[0] = p.x + p.y; }
        { float2 p = up2(s01); sv0[1] = p.x + p.y; }
        { float2 p = up2(s02); sv0[2] = p.x + p.y; }
        { float2 p = up2(s03); sv0[3] = p.x + p.y; }
        { float2 p = up2(s10); sv1[0] = p.x + p.y; }
        { float2 p = up2(s11); sv1[1] = p.x + p.y; }
        { float2 p = up2(s12); sv1[2] = p.x + p.y; }
        { float2 p = up2(s13); sv1[3] = p.x + p.y; }

        if (ch == s0) {
            // establish exp offsets C_j = min over first-chunk scores
            *(float4*)(scb + wp * 8 + 4 * jh)        = make_float4(sv0[0], sv0[1], sv0[2], sv0[3]);
            *(float4*)(scb + (wp + 64) * 8 + 4 * jh) = make_float4(sv1[0], sv1[1], sv1[2], sv1[3]);
            __syncthreads();
#pragma unroll
            for (int k = 0; k < 2; k++) {          // warp wid handles j=2wid+k
                int j = 2 * wid + k;
                float mn = 3.4e38f;
#pragma unroll
                for (int r = 0; r < 4; r++)
                    mn = fminf(mn, scb[(lane + 32 * r) * 8 + j]);
#pragma unroll
                for (int o = 16; o; o >>= 1)
                    mn = fminf(mn, __shfl_xor_sync(0xffffffffu, mn, o));
                if (lane == 0) Cs[j] = mn;
            }
            __syncthreads();
#pragma unroll
            for (int k = 0; k < 4; k++) Cr[k] = Cs[4 * jh + k];
        }

        float e0[4], e1[4];
#pragma unroll
        for (int k = 0; k < 4; k++) {
            e0[k] = __expf(Cr[k] - sv0[k]);
            e1[k] = __expf(Cr[k] - sv1[k]);
            zp[k] += e0[k] + e1[k];
            qp[k] += e0[k] * sv0[k] + e1[k] * sv1[k];
        }
        *(float4*)(scb + wp * 8 + 4 * jh)        = make_float4(e0[0], e0[1], e0[2], e0[3]);
        *(float4*)(scb + (wp + 64) * 8 + 4 * jh) = make_float4(e1[0], e1[1], e1[2], e1[3]);
        __syncthreads();

        // ---- best accumulate: warp owns 32-w slice, j-pairs packed ----
        const int w0 = wid * 32;
        const ulonglong2* arow = (const ulonglong2*)scb;
#pragma unroll 8
        for (int i = 0; i < 32; i++) {
            int wl = w0 + i;
            ulonglong2 A0 = arow[wl * 2];        // (j0,j1),(j2,j3)
            ulonglong2 A1 = arow[wl * 2 + 1];    // (j4,j5),(j6,j7)
            float x0 = tile[wl * 65 + lane];
            float x1 = tile[wl * 65 + 32 + lane];
            unsigned long long xx0 = pk2(x0, x0);
            unsigned long long xx1 = pk2(x1, x1);
            fma2(accP[0][0], A0.x, xx0); fma2(accP[0][1], A0.y, xx0);
            fma2(accP[0][2], A1.x, xx0); fma2(accP[0][3], A1.y, xx0);
            fma2(accP[1][0], A0.x, xx1); fma2(accP[1][1], A0.y, xx1);
            fma2(accP[1][2], A1.x, xx1); fma2(accP[1][3], A1.y, xx1);
        }
    }

    // ---- Z/Q reduction ----
#pragma unroll
    for (int o = 16; o; o >>= 1)
#pragma unroll
        for (int k = 0; k < 4; k++) {
            zp[k] += __shfl_xor_sync(0xffffffffu, zp[k], o);
            qp[k] += __shfl_xor_sync(0xffffffffu, qp[k], o);
        }
    __syncthreads();                       // chunk loop done; reuse tile
    if (lane == 0) {
#pragma unroll
        for (int k = 0; k < 4; k++) { zw[wid * 4 + k] = zp[k]; qw[wid * 4 + k] = qp[k]; }
    }
    // dump best partials (warp-sliced) into tile
    float* red = tile;
#pragma unroll
    for (int p = 0; p < 4; p++) {
        float2 v0 = up2(accP[0][p]);
        float2 v1 = up2(accP[1][p]);
        red[(wid * 8 + 2 * p    ) * 64 + lane]      = v0.x;
        red[(wid * 8 + 2 * p + 1) * 64 + lane]      = v0.y;
        red[(wid * 8 + 2 * p    ) * 64 + 32 + lane] = v1.x;
        red[(wid * 8 + 2 * p + 1) * 64 + 32 + lane] = v1.y;
    }
    __syncthreads();
    if (t < 8) {                   // j = t
        int h = t >> 2, k = t & 3;
        float Z = zw[(2 * h) * 4 + k] + zw[(2 * h + 1) * 4 + k];
        float Q = qw[(2 * h) * 4 + k] + qw[(2 * h + 1) * 4 + k];
        int o = (zi * NB + b) * NJ + t;
        p_Z[o] = Z;
        p_Q[o] = Q;
        p_C[o] = Cs[t];
    }
    // raw best partials -> gmem (no normalization)
#pragma unroll
    for (int rep = 0; rep < 2; rep++) {
        const int j = wid + 4 * rep;
        float b0 = 0.f, b1 = 0.f;
#pragma unroll
        for (int w4 = 0; w4 < 4; w4++) {
            b0 += red[(w4 * 8 + j) * 64 + lane];
            b1 += red[(w4 * 8 + j) * 64 + 32 + lane];
        }
        size_t o = ((size_t)(zi * NJ + j) * NB + b) * 64;
        p_best[o + lane]      = b0;
        p_best[o + 32 + lane] = b1;
    }
}

// =============================================================================
// Kernel A2: combine splits -> g_best, g_conf, body path -> g_cv.
// grid = 512 (b), 128 threads.
// =============================================================================
extern "C" __global__ void __launch_bounds__(128)
kA2(const float* __restrict__ gammas, const float* __restrict__ body_w,
    const float* __restrict__ body_b)
{
    __shared__ float sC[24], sZ[24], sQ[24];
    __shared__ float es[NSPLIT * 8];     // e^{C-Ci}/Z per (zi,j)
    __shared__ float smq[8];
    __shared__ float sgav[8];
    __shared__ float sbest[512];
    __shared__ float sred[256];

    const int t = threadIdx.x;
    const int b = blockIdx.x;

    if (t < 24) {                         // parallel partial loads
        int zi = t >> 3, j = t & 7;
        int idx = (zi * NB + b) * NJ + j;
        sC[t] = p_C[idx];
        sZ[t] = p_Z[idx];
        sQ[t] = p_Q[idx];
    }
    if (t >= 32 && t < 40) {              // g_avg (separate warp)
        int j = t - 32;
        float s = 0.f;
        for (int l = 0; l < NL; l++) {
            float g = gammas[j * 64 + l];
            s += fminf(fmaxf(g, 0.f), 1.f);
        }
        sgav[j] = s * (1.f / 64.f);
    }
    __syncthreads();
    if (t < 8) {
        float C0 = sC[t], C1 = sC[8 + t], C2 = sC[16 + t];
        float C = fminf(C0, fminf(C1, C2));
        float f0 = __expf(C - C0), f1 = __expf(C - C1), f2 = __expf(C - C2);
        float Z = sZ[t] * f0 + sZ[8 + t] * f1 + sZ[16 + t] * f2;
        float Q = sQ[t] * f0 + sQ[8 + t] * f1 + sQ[16 + t] * f2;
        float r = 1.f / Z;
        es[0 * 8 + t] = f0 * r;
        es[1 * 8 + t] = f1 * r;
        es[2 * 8 + t] = f2 * r;
        smq[t] = Q * r;
    }
    __syncthreads();
    if (t == 0) {
        float tm = 0.f;
#pragma unroll
        for (int j = 0; j < 8; j++) tm += smq[j];
        g_conf[b] = expf(-tm);
    }

    // combine best
#pragma unroll
    for (int r = 0; r < 4; r++) {
        int idx = t + 128 * r;             // 0..511
        int j = idx >> 6, l = idx & 63;
        float v = p_best[((size_t)(0 * NJ + j) * NB + b) * 64 + l] * es[0 * 8 + j]
                + p_best[((size_t)(1 * NJ + j) * NB + b) * 64 + l] * es[1 * 8 + j]
                + p_best[((size_t)(2 * NJ + j) * NB + b) * 64 + l] * es[2 * 8 + j];
        sbest[idx] = v;
        g_best[((size_t)j * NB + b) * 64 + l] = v;
    }
    __syncthreads();

    // body path: 256 (j,i) items over 128 threads
    float outv[2];
#pragma unroll
    for (int rep = 0; rep < 2; rep++) {
        int idx = t + 128 * rep;
        int j = idx >> 5, i = idx & 31;
        const float4* bwp = (const float4*)(body_w + (j * NI + i) * NL);
        const float4* bsp = (const float4*)(sbest + j * 64);
        float d = 0.f;
#pragma unroll
        for (int l4 = 0; l4 < 16; l4++) {
            float4 w4 = bwp[l4];
            float4 x4 = bsp[l4];
            d += x4.x * w4.x + x4.y * w4.y + x4.z * w4.z + x4.w * w4.w;
        }
        d += body_b[j * NI + i];
        outv[rep] = sgav[j] * d;
    }
#pragma unroll
    for (int rep = 0; rep < 2; rep++) sred[t + 128 * rep] = outv[rep];
    __syncthreads();
    if (t < 32) {
        float s = 0.f;
#pragma unroll
        for (int j = 0; j < 8; j++) s += sred[j * 32 + t];
        g_cv[b * 32 + t] = s;
    }
}

// =============================================================================
// Kernel B: slot selector. grid = (16 b-tiles, 8 j, 4 k-quarters), 256 thr.
// 8 chunks of 64 k per CTA. Phase b: 2k x 4b FFMA2. Phase c: all 256 threads
// (b x 2 l_slots x 4 i-quarters; reduce via smem aliased onto w_s).
// smem: w_s 64*66=4224 (66 pad => 8B-aligned float2 rows), lg 64*32=2048,
//       bs 64*32=2048 -> 33.3 KB, occ 5 => 740 slots >= 512 CTAs: single wave.
// =============================================================================
#define B_WS  0
#define B_LG  (64*66)                  // 4224
#define B_BS  (B_LG + 64*32)           // 6272
#define B_SMEM_FLOATS (B_BS + 64*32)   // 8320 floats = 33280 B

extern "C" __global__ void __launch_bounds__(256, 5)
kB(const float* __restrict__ slot_w, const float* __restrict__ slot_b)
{
    extern __shared__ float sm[];
    float* w_s = sm + B_WS;
    float* lg  = sm + B_LG;
    float* bs  = sm + B_BS;
    float* pm  = sm + B_WS;              // phase-c scratch aliases w_s[0..511]

    const int t  = threadIdx.x;
    const int j  = blockIdx.y;
    const int b0 = blockIdx.x * 32;
    const int kq = blockIdx.z;           // k-quarter (512 k each)

    const int q  = t & 7;                // phase b: b quad = q*4..q*4+3
    const int ko = t >> 3;               // phase b: k = ko*2+kk (0..63)
    const int cb = t & 31;               // phase c: b
    const int ls = (t >> 5) & 1;         // phase c: l_slot (0..1)
    const int iq = t >> 6;               // phase c: i quarter (0..3), 8 i each
    const int tb = (ls << 5) | cb;       // phase c reduction base

    // stage best transposed: bs[l*32 + b]
    {
        int bb = t >> 3;                 // 0..31
        int l0 = (t & 7) * 8;            // 8 consecutive l
        const float4* gp = (const float4*)(&g_best[((size_t)j * NB + b0 + bb) * 64 + l0]);
        float4 v0 = gp[0], v1 = gp[1];
        bs[(l0+0)*32+bb]=v0.x; bs[(l0+1)*32+bb]=v0.y;
        bs[(l0+2)*32+bb]=v0.z; bs[(l0+3)*32+bb]=v0.w;
        bs[(l0+4)*32+bb]=v1.x; bs[(l0+5)*32+bb]=v1.y;
        bs[(l0+6)*32+bb]=v1.z; bs[(l0+7)*32+bb]=v1.w;
    }

    float accI[8];
#pragma unroll
    for (int i = 0; i < 8; i++) accI[i] = 0.f;

    const float* swj = slot_w + (size_t)j * (NK * NL) + (size_t)kq * 512 * 64;
    const float* sbj = slot_b + j * NK + kq * 512;

    for (int ch = 0; ch < 8; ch++) {
        __syncthreads();
        // stage 64 k-rows of weights (64*64 floats = 1024 float4)
        const float4* src = (const float4*)(swj + ch * 64 * 64);
#pragma unroll
        for (int qq = 0; qq < 4; qq++) {
            int f = t + 256 * qq;           // 0..1023
            int row = f >> 4, c4 = f & 15;
            float4 v = src[f];
            float* dst = w_s + row * 66 + c4 * 4;
            dst[0] = v.x; dst[1] = v.y; dst[2] = v.z; dst[3] = v.w;
        }
        __syncthreads();

        // ---- phase b: logits, 2k x 4b, f32x2 ----
        unsigned long long acc[2][2];
#pragma unroll
        for (int kk = 0; kk < 2; kk++) {
            float svv = sbj[ch * 64 + ko * 2 + kk];
            acc[kk][0] = pk2(svv, svv);
            acc[kk][1] = pk2(svv, svv);
        }
#pragma unroll 8
        for (int l = 0; l < 64; l += 2) {
            ulonglong2 p0 = *(const ulonglong2*)(bs + l * 32 + q * 4);
            ulonglong2 p1 = *(const ulonglong2*)(bs + (l + 1) * 32 + q * 4);
#pragma unroll
            for (int kk = 0; kk < 2; kk++) {
                float2 w2 = *(const float2*)(w_s + (ko * 2 + kk) * 66 + l);
                unsigned long long wa = pk2(w2.x, w2.x);
                unsigned long long wb = pk2(w2.y, w2.y);
                fma2(acc[kk][0], p0.x, wa); fma2(acc[kk][1], p0.y, wa);
                fma2(acc[kk][0], p1.x, wb); fma2(acc[kk][1], p1.y, wb);
            }
        }
#pragma unroll
        for (int kk = 0; kk < 2; kk++) {
            ulonglong2 o; o.x = acc[kk][0]; o.y = acc[kk][1];
            *(ulonglong2*)(lg + (ko * 2 + kk) * 32 + q * 4) = o;
        }
        __syncthreads();

        // ---- phase c: (b=cb, l_slot=ls), i = iq*8..iq*8+7 ----
        {
            float lv[8];
            float m8 = -3.4e38f;
#pragma unroll
            for (int i = 0; i < 8; i++) {
                lv[i] = lg[(ls * 32 + iq * 8 + i) * 32 + cb];
                m8 = fmaxf(m8, lv[i]);
            }
            pm[t] = m8;                       // pm[0..255] = maxes
            __syncthreads();
            float m = fmaxf(fmaxf(pm[tb], pm[tb + 64]),
                            fmaxf(pm[tb + 128], pm[tb + 192]));
            float s8 = 0.f;
#pragma unroll
            for (int i = 0; i < 8; i++) {
                lv[i] = __expf(lv[i] - m);
                s8 += lv[i];
            }
            pm[256 + t] = s8;                 // pm[256..511] = sums (disjoint)
            __syncthreads();
            float Z = pm[256 + tb] + pm[256 + tb + 64]
                    + pm[256 + tb + 128] + pm[256 + tb + 192];
            int l = kq * 16 + ch * 2 + ls;
            float s = bs[l * 32 + cb] / Z;
#pragma unroll
            for (int i = 0; i < 8; i++) accI[i] += lv[i] * s;
        }
    }
    __syncthreads();

    // reduce the 2 l_slot partials per b (red2 aliases w_s; rows pad 33)
    float* red2 = w_s;
#pragma unroll
    for (int i = 0; i < 8; i++)
        red2[(ls * 32 + cb) * 33 + iq * 8 + i] = accI[i];
    __syncthreads();
#pragma unroll
    for (int r = 0; r < 4; r++) {
        int e = t * 4 + r;               // 0..1023
        int bb = e >> 5, i = e & 31;
        float s = red2[bb * 33 + i] + red2[(32 + bb) * 33 + i];
        g_cvp[(((size_t)kq * NJ + j) * NB + b0 + bb) * 32 + i] = s;
    }
}

// =============================================================================
// Kernel C: cv_total = body + 32 slot partials; out = conf * (cv@W^T + b)
// grid = 128 CTAs x 128 threads, 4 b per CTA (head_w staged once per CTA).
// =============================================================================
extern "C" __global__ void __launch_bounds__(128)
kC(const float* __restrict__ head_w, const float* __restrict__ head_b,
   float* __restrict__ out)
{
    __shared__ float hw[NO * 33];
    __shared__ float cvt[4 * 32];
    __shared__ float cf[4];
    const int t  = threadIdx.x;
    const int b0 = blockIdx.x * 4;

#pragma unroll
    for (int r = 0; r < 32; r++) {
        int e = t + 128 * r;             // 0..4095
        int o = e >> 5, i = e & 31;
        hw[o * 33 + i] = head_w[e];
    }
    {
        int bl = t >> 5, i = t & 31;
        int b = b0 + bl;
        float v = g_cv[b * 32 + i];
#pragma unroll
        for (int p = 0; p < 32; p++)
            v += g_cvp[((size_t)p * NB + b) * 32 + i];
        cvt[bl * 32 + i] = v;
    }
    if (t < 4) cf[t] = g_conf[b0 + t];
    __syncthreads();

    float hb = head_b[t];
#pragma unroll
    for (int bl = 0; bl < 4; bl++) {
        float d = hb;
#pragma unroll
        for (int i = 0; i < 32; i++) d += cvt[bl * 32 + i] * hw[t * 33 + i];
        out[(b0 + bl) * NO + t] = cf[bl] * d;
    }
}

// =============================================================================
extern "C" void kernel_launch(void* const* d_in, const int* in_sizes, int n_in,
                              void* d_out, int out_size)
{
    const float* wm  = (const float*)d_in[0];
    const float* cst = (const float*)d_in[1];
    const float* gam = (const float*)d_in[2];
    const float* bw  = (const float*)d_in[3];
    const float* bb  = (const float*)d_in[4];
    const float* sw  = (const float*)d_in[5];
    const float* sb  = (const float*)d_in[6];
    const float* hwp = (const float*)d_in[7];
    const float* hbp = (const float*)d_in[8];
    float* out = (float*)d_out;

    cudaFuncSetAttribute(kA1, cudaFuncAttributeMaxDynamicSharedMemorySize,
                         A_SMEM_FLOATS * 4);
    cudaFuncSetAttribute(kB, cudaFuncAttributeMaxDynamicSharedMemorySize,
                         B_SMEM_FLOATS * 4);

    dim3 ga(NB, NSPLIT);
    kA1<<<ga, 128, A_SMEM_FLOATS * 4>>>(wm, cst, gam);
    kA2<<<NB, 128>>>(gam, bw, bb);
    dim3 gb(16, 8, 4);
    kB<<<gb, 256, B_SMEM_FLOATS * 4>>>(sw, sb);
    kC<<<128, 128>>>(hwp, hbp, out);
}

// round 17
// speedup vs baseline: 1.0007x; 1.0007x over previous
#include <cuda_runtime.h>
#include <math.h>

// Problem shapes (fixed)
#define NB 512
#define NW 1024
#define NL 64
#define NJ 8
#define NI 32
#define NO 128
#define NK 2048   // L*I
#define NSPLIT 3  // w-splits of kA: chunks {3,3,2} x 128 w

// ---------------- device scratch (no allocations allowed) -------------------
__device__ float g_best[NJ * NB * NL];       // best[j][b][l]        (1 MB)
__device__ float g_cv  [NB * NI];            // body contribution
__device__ float g_cvp [4 * NJ * NB * NI];   // slot partials [kq][j][b][i]
__device__ float g_conf[NB];                 // exp(-total_mq)
__device__ float p_Z   [NSPLIT * NB * NJ];   // partial Z   [zi][b][j]
__device__ float p_Q   [NSPLIT * NB * NJ];   // partial sum e*s
__device__ float p_C   [NSPLIT * NB * NJ];   // per-split exp offset
__device__ float p_best[NSPLIT * NJ * NB * NL];  // raw sum e*x (3 MB)

// ---------------- packed f32x2 helpers (Blackwell FFMA2) --------------------
static __device__ __forceinline__ unsigned long long pk2(float x, float y) {
    unsigned long long r;
    asm("mov.b64 %0, {%1,%2};" : "=l"(r) : "f"(x), "f"(y));
    return r;
}
static __device__ __forceinline__ void fma2(unsigned long long& d,
                                            unsigned long long a,
                                            unsigned long long b) {
    asm("fma.rn.f32x2 %0, %1, %2, %0;" : "+l"(d) : "l"(a), "l"(b));
}
static __device__ __forceinline__ float2 up2(unsigned long long v) {
    float2 r;
    asm("mov.b64 {%0,%1}, %2;" : "=f"(r.x), "=f"(r.y) : "l"(v));
    return r;
}

// =============================================================================
// Kernel A1: partial scores/softmax/best for one (b, w-split).   (R14 verbatim)
// grid = (512 b, 3 zi), 128 threads. zi 0/1: chunks 0-2/3-5; zi 2: chunks 6-7.
// =============================================================================
#define CW     128
#define A_COEF 0
#define A_TILE 1024
#define A_SCB  (A_TILE + 128*65)      // 9344
#define A_AS   (A_SCB + 1024)         // 10368
#define A_CS   (A_AS + 8)
#define A_ZW   (A_CS + 8)             // 4 warps x 4
#define A_QW   (A_ZW + 16)
#define A_SMEM_FLOATS (A_QW + 16)     // 10408

extern "C" __global__ void __launch_bounds__(128, 5)
kA1(const float* __restrict__ wm, const float* __restrict__ constants,
    const float* __restrict__ gammas)
{
    extern __shared__ float sm[];
    unsigned long long* coefT = (unsigned long long*)(sm + A_COEF); // [l*8+j]
    float* tile = sm + A_TILE;
    float* scb  = sm + A_SCB;
    float* As   = sm + A_AS;
    float* Cs   = sm + A_CS;
    float* zw   = sm + A_ZW;
    float* qw   = sm + A_QW;

    const int t    = threadIdx.x;
    const int b    = blockIdx.x;
    const int zi   = blockIdx.y;
    const int lane = t & 31;
    const int wid  = t >> 5;          // 0..3
    const int wp   = t & 63;          // score: w in {wp, wp+64}
    const int jh   = t >> 6;          // score: j in {4jh..4jh+3}

    const int s0  = zi * 3;                    // first chunk
    const int nch = (zi < 2) ? 3 : 2;          // chunk count

    // ---- Phase 0: coefficients (scratch in tile) ----
    for (int e = t; e < NJ * NL; e += 128) {
        float g = gammas[e];
        g = fminf(fmaxf(g, 0.f), 1.f);
        float w1 = 1.f - g;
        float c  = constants[e];
        int j = e >> 6, l = e & 63;
        coefT[l * 8 + j] = pk2(-2.f * w1 * c, w1);
        tile[e] = w1 * c * c;
    }
    __syncthreads();
    if (t < 8) {
        float a = 0.f;
        for (int l = 0; l < NL; l++) a += tile[t * 64 + l];
        As[t] = a;
    }
    __syncthreads();

    float Areg[4];
#pragma unroll
    for (int k = 0; k < 4; k++) Areg[k] = As[4 * jh + k];
    const ulonglong2* cT = (const ulonglong2*)coefT;   // [l*4 + 2jh (+1)]
    const float* wmb = wm + (size_t)b * (NW * NL);

    unsigned long long accP[2][4];        // best accum: [x-half][(j,j+1) pair]
#pragma unroll
    for (int h = 0; h < 2; h++)
#pragma unroll
        for (int p = 0; p < 4; p++) accP[h][p] = pk2(0.f, 0.f);
    float zp[4] = {0.f, 0.f, 0.f, 0.f};
    float qp[4] = {0.f, 0.f, 0.f, 0.f};
    float Cr[4] = {0.f, 0.f, 0.f, 0.f};   // exp offsets (set @ first chunk)

    for (int ch = s0; ch < s0 + nch; ch++) {
        __syncthreads();
        // ---- stage 128-w chunk (128 threads, 16 float4 each) ----
        const float4* src = (const float4*)(wmb + ch * CW * 64);
#pragma unroll
        for (int qq = 0; qq < 16; qq++) {
            int f = t + 128 * qq;            // 0..2047 float4s
            int row = f >> 4, c4 = f & 15;
            float4 v = src[f];
            float* dst = tile + row * 65 + c4 * 4;
            dst[0] = v.x; dst[1] = v.y; dst[2] = v.z; dst[3] = v.w;
        }
        __syncthreads();

        // ---- scores: w in {wp, wp+64}, j = 4jh..4jh+3 ----
        unsigned long long s00 = pk2(Areg[0], 0.f);
        unsigned long long s01 = pk2(Areg[1], 0.f);
        unsigned long long s02 = pk2(Areg[2], 0.f);
        unsigned long long s03 = pk2(Areg[3], 0.f);
        unsigned long long s10 = s00, s11 = s01, s12 = s02, s13 = s03;
        const float* r0 = tile + wp * 65;
        const float* r1 = tile + (wp + 64) * 65;
#pragma unroll 16
        for (int l = 0; l < 64; l++) {
            float x0 = r0[l], x1 = r1[l];
            unsigned long long a0 = pk2(x0, x0 * x0);
            unsigned long long a1 = pk2(x1, x1 * x1);
            ulonglong2 ccA = cT[l * 4 + 2 * jh];
            ulonglong2 ccB = cT[l * 4 + 2 * jh + 1];
            fma2(s00, a0, ccA.x); fma2(s01, a0, ccA.y);
            fma2(s02, a0, ccB.x); fma2(s03, a0, ccB.y);
            fma2(s10, a1, ccA.x); fma2(s11, a1, ccA.y);
            fma2(s12, a1, ccB.x); fma2(s13, a1, ccB.y);
        }
        float sv0[4], sv1[4];
        { float2 p = up2(s00); sv0[0] = p.x + p.y; }
        { float2 p = up2(s01); sv0[1] = p.x + p.y; }
        { float2 p = up2(s02); sv0[2] = p.x + p.y; }
        { float2 p = up2(s03); sv0[3] = p.x + p.y; }
        { float2 p = up2(s10); sv1[0] = p.x + p.y; }
        { float2 p = up2(s11); sv1[1] = p.x + p.y; }
        { float2 p = up2(s12); sv1[2] = p.x + p.y; }
        { float2 p = up2(s13); sv1[3] = p.x + p.y; }

        if (ch == s0) {
            // establish exp offsets C_j = min over first-chunk scores
            *(float4*)(scb + wp * 8 + 4 * jh)        = make_float4(sv0[0], sv0[1], sv0[2], sv0[3]);
            *(float4*)(scb + (wp + 64) * 8 + 4 * jh) = make_float4(sv1[0], sv1[1], sv1[2], sv1[3]);
            __syncthreads();
#pragma unroll
            for (int k = 0; k < 2; k++) {          // warp wid handles j=2wid+k
                int j = 2 * wid + k;
                float mn = 3.4e38f;
#pragma unroll
                for (int r = 0; r < 4; r++)
                    mn = fminf(mn, scb[(lane + 32 * r) * 8 + j]);
#pragma unroll
                for (int o = 16; o; o >>= 1)
                    mn = fminf(mn, __shfl_xor_sync(0xffffffffu, mn, o));
                if (lane == 0) Cs[j] = mn;
            }
            __syncthreads();
#pragma unroll
            for (int k = 0; k < 4; k++) Cr[k] = Cs[4 * jh + k];
        }

        float e0[4], e1[4];
#pragma unroll
        for (int k = 0; k < 4; k++) {
            e0[k] = __expf(Cr[k] - sv0[k]);
            e1[k] = __expf(Cr[k] - sv1[k]);
            zp[k] += e0[k] + e1[k];
            qp[k] += e0[k] * sv0[k] + e1[k] * sv1[k];
        }
        *(float4*)(scb + wp * 8 + 4 * jh)        = make_float4(e0[0], e0[1], e0[2], e0[3]);
        *(float4*)(scb + (wp + 64) * 8 + 4 * jh) = make_float4(e1[0], e1[1], e1[2], e1[3]);
        __syncthreads();

        // ---- best accumulate: warp owns 32-w slice, j-pairs packed ----
        const int w0 = wid * 32;
        const ulonglong2* arow = (const ulonglong2*)scb;
#pragma unroll 8
        for (int i = 0; i < 32; i++) {
            int wl = w0 + i;
            ulonglong2 A0 = arow[wl * 2];        // (j0,j1),(j2,j3)
            ulonglong2 A1 = arow[wl * 2 + 1];    // (j4,j5),(j6,j7)
            float x0 = tile[wl * 65 + lane];
            float x1 = tile[wl * 65 + 32 + lane];
            unsigned long long xx0 = pk2(x0, x0);
            unsigned long long xx1 = pk2(x1, x1);
            fma2(accP[0][0], A0.x, xx0); fma2(accP[0][1], A0.y, xx0);
            fma2(accP[0][2], A1.x, xx0); fma2(accP[0][3], A1.y, xx0);
            fma2(accP[1][0], A0.x, xx1); fma2(accP[1][1], A0.y, xx1);
            fma2(accP[1][2], A1.x, xx1); fma2(accP[1][3], A1.y, xx1);
        }
    }

    // ---- Z/Q reduction ----
#pragma unroll
    for (int o = 16; o; o >>= 1)
#pragma unroll
        for (int k = 0; k < 4; k++) {
            zp[k] += __shfl_xor_sync(0xffffffffu, zp[k], o);
            qp[k] += __shfl_xor_sync(0xffffffffu, qp[k], o);
        }
    __syncthreads();                       // chunk loop done; reuse tile
    if (lane == 0) {
#pragma unroll
        for (int k = 0; k < 4; k++) { zw[wid * 4 + k] = zp[k]; qw[wid * 4 + k] = qp[k]; }
    }
    // dump best partials (warp-sliced) into tile
    float* red = tile;
#pragma unroll
    for (int p = 0; p < 4; p++) {
        float2 v0 = up2(accP[0][p]);
        float2 v1 = up2(accP[1][p]);
        red[(wid * 8 + 2 * p    ) * 64 + lane]      = v0.x;
        red[(wid * 8 + 2 * p + 1) * 64 + lane]      = v0.y;
        red[(wid * 8 + 2 * p    ) * 64 + 32 + lane] = v1.x;
        red[(wid * 8 + 2 * p + 1) * 64 + 32 + lane] = v1.y;
    }
    __syncthreads();
    if (t < 8) {                   // j = t
        int h = t >> 2, k = t & 3;
        float Z = zw[(2 * h) * 4 + k] + zw[(2 * h + 1) * 4 + k];
        float Q = qw[(2 * h) * 4 + k] + qw[(2 * h + 1) * 4 + k];
        int o = (zi * NB + b) * NJ + t;
        p_Z[o] = Z;
        p_Q[o] = Q;
        p_C[o] = Cs[t];
    }
    // raw best partials -> gmem (no normalization)
#pragma unroll
    for (int rep = 0; rep < 2; rep++) {
        const int j = wid + 4 * rep;
        float b0 = 0.f, b1 = 0.f;
#pragma unroll
        for (int w4 = 0; w4 < 4; w4++) {
            b0 += red[(w4 * 8 + j) * 64 + lane];
            b1 += red[(w4 * 8 + j) * 64 + 32 + lane];
        }
        size_t o = ((size_t)(zi * NJ + j) * NB + b) * 64;
        p_best[o + lane]      = b0;
        p_best[o + 32 + lane] = b1;
    }
}

// =============================================================================
// Kernel A2: combine splits -> g_best, g_conf, body path -> g_cv. (R14 verbatim)
// =============================================================================
extern "C" __global__ void __launch_bounds__(128)
kA2(const float* __restrict__ gammas, const float* __restrict__ body_w,
    const float* __restrict__ body_b)
{
    __shared__ float sC[24], sZ[24], sQ[24];
    __shared__ float es[NSPLIT * 8];     // e^{C-Ci}/Z per (zi,j)
    __shared__ float smq[8];
    __shared__ float sgav[8];
    __shared__ float sbest[512];
    __shared__ float sred[256];

    const int t = threadIdx.x;
    const int b = blockIdx.x;

    if (t < 24) {                         // parallel partial loads
        int zi = t >> 3, j = t & 7;
        int idx = (zi * NB + b) * NJ + j;
        sC[t] = p_C[idx];
        sZ[t] = p_Z[idx];
        sQ[t] = p_Q[idx];
    }
    if (t >= 32 && t < 40) {              // g_avg (separate warp)
        int j = t - 32;
        float s = 0.f;
        for (int l = 0; l < NL; l++) {
            float g = gammas[j * 64 + l];
            s += fminf(fmaxf(g, 0.f), 1.f);
        }
        sgav[j] = s * (1.f / 64.f);
    }
    __syncthreads();
    if (t < 8) {
        float C0 = sC[t], C1 = sC[8 + t], C2 = sC[16 + t];
        float C = fminf(C0, fminf(C1, C2));
        float f0 = __expf(C - C0), f1 = __expf(C - C1), f2 = __expf(C - C2);
        float Z = sZ[t] * f0 + sZ[8 + t] * f1 + sZ[16 + t] * f2;
        float Q = sQ[t] * f0 + sQ[8 + t] * f1 + sQ[16 + t] * f2;
        float r = 1.f / Z;
        es[0 * 8 + t] = f0 * r;
        es[1 * 8 + t] = f1 * r;
        es[2 * 8 + t] = f2 * r;
        smq[t] = Q * r;
    }
    __syncthreads();
    if (t == 0) {
        float tm = 0.f;
#pragma unroll
        for (int j = 0; j < 8; j++) tm += smq[j];
        g_conf[b] = expf(-tm);
    }

    // combine best
#pragma unroll
    for (int r = 0; r < 4; r++) {
        int idx = t + 128 * r;             // 0..511
        int j = idx >> 6, l = idx & 63;
        float v = p_best[((size_t)(0 * NJ + j) * NB + b) * 64 + l] * es[0 * 8 + j]
                + p_best[((size_t)(1 * NJ + j) * NB + b) * 64 + l] * es[1 * 8 + j]
                + p_best[((size_t)(2 * NJ + j) * NB + b) * 64 + l] * es[2 * 8 + j];
        sbest[idx] = v;
        g_best[((size_t)j * NB + b) * 64 + l] = v;
    }
    __syncthreads();

    // body path: 256 (j,i) items over 128 threads
    float outv[2];
#pragma unroll
    for (int rep = 0; rep < 2; rep++) {
        int idx = t + 128 * rep;
        int j = idx >> 5, i = idx & 31;
        const float4* bwp = (const float4*)(body_w + (j * NI + i) * NL);
        const float4* bsp = (const float4*)(sbest + j * 64);
        float d = 0.f;
#pragma unroll
        for (int l4 = 0; l4 < 16; l4++) {
            float4 w4 = bwp[l4];
            float4 x4 = bsp[l4];
            d += x4.x * w4.x + x4.y * w4.y + x4.z * w4.z + x4.w * w4.w;
        }
        d += body_b[j * NI + i];
        outv[rep] = sgav[j] * d;
    }
#pragma unroll
    for (int rep = 0; rep < 2; rep++) sred[t + 128 * rep] = outv[rep];
    __syncthreads();
    if (t < 32) {
        float s = 0.f;
#pragma unroll
        for (int j = 0; j < 8; j++) s += sred[j * 32 + t];
        g_cv[b * 32 + t] = s;
    }
}

// =============================================================================
// Kernel B: slot selector. grid = (16 b-tiles, 8 j, 4 k-quarters), 256 thr.
// 4 chunks of 128 k; each chunk's logits done in TWO 64-k halves so lg is
// half-size. Phase b: 2k x 4b FFMA2 (lg pad 36: conflict-free 16B stores).
// Phase c: no max-subtraction (logits |x|<~6, exp safe); 4-thread i-quarter
// groups exchange partial sums once via pm.
// smem: w_s 128*66=8448, lg 64*36=2304, bs 64*32=2048, pm 256
//   = 13056 floats = 52224 B -> occ 4 (4*(52224+1024) <= 228KB), 592 slots
//   >= 512 CTAs: SINGLE WAVE, reg cap 64.
// =============================================================================
#define B_WS  0
#define B_LG  8448
#define B_BS  (B_LG + 64*36)           // 10752
#define B_PM  (B_BS + 64*32)           // 12800
#define B_SMEM_FLOATS (B_PM + 256)     // 13056

extern "C" __global__ void __launch_bounds__(256, 4)
kB(const float* __restrict__ slot_w, const float* __restrict__ slot_b)
{
    extern __shared__ float sm[];
    float* w_s = sm + B_WS;
    float* lg  = sm + B_LG;
    float* bs  = sm + B_BS;
    float* pm  = sm + B_PM;

    const int t  = threadIdx.x;
    const int j  = blockIdx.y;
    const int b0 = blockIdx.x * 32;
    const int kq = blockIdx.z;           // k-quarter (512 k each)

    const int q  = t & 7;                // phase b: b quad = q*4..q*4+3
    const int ko = t >> 3;               // phase b: local k = ko*2+kk (0..63)
    const int cb = t & 31;               // phase c: b
    const int ls = (t >> 5) & 1;         // phase c: l_slot in half (0..1)
    const int iq = t >> 6;               // phase c: i quarter (0..3)
    const int tb = (ls << 5) | cb;       // phase c exchange base

    // stage best transposed: bs[l*32 + b]
    {
        int bb = t >> 3;                 // 0..31
        int l0 = (t & 7) * 8;            // 8 consecutive l
        const float4* gp = (const float4*)(&g_best[((size_t)j * NB + b0 + bb) * 64 + l0]);
        float4 v0 = gp[0], v1 = gp[1];
        bs[(l0+0)*32+bb]=v0.x; bs[(l0+1)*32+bb]=v0.y;
        bs[(l0+2)*32+bb]=v0.z; bs[(l0+3)*32+bb]=v0.w;
        bs[(l0+4)*32+bb]=v1.x; bs[(l0+5)*32+bb]=v1.y;
        bs[(l0+6)*32+bb]=v1.z; bs[(l0+7)*32+bb]=v1.w;
    }

    float accI[8];
#pragma unroll
    for (int i = 0; i < 8; i++) accI[i] = 0.f;

    const float* swj = slot_w + (size_t)j * (NK * NL) + (size_t)kq * 512 * 64;
    const float* sbj = slot_b + j * NK + kq * 512;

    for (int ch = 0; ch < 4; ch++) {
        __syncthreads();
        // stage 128 k-rows of weights (128*64 floats = 2048 float4)
        const float4* src = (const float4*)(swj + ch * 128 * 64);
#pragma unroll
        for (int qq = 0; qq < 8; qq++) {
            int f = t + 256 * qq;           // 0..2047
            int row = f >> 4, c4 = f & 15;
            float4 v = src[f];
            float* dst = w_s + row * 66 + c4 * 4;
            dst[0] = v.x; dst[1] = v.y; dst[2] = v.z; dst[3] = v.w;
        }
        __syncthreads();

#pragma unroll
        for (int hf = 0; hf < 2; hf++) {
            // ---- phase b: logits for 64 k-rows, 2k x 4b, f32x2 ----
            unsigned long long acc[2][2];
#pragma unroll
            for (int kk = 0; kk < 2; kk++) {
                float svv = sbj[ch * 128 + hf * 64 + ko * 2 + kk];
                acc[kk][0] = pk2(svv, svv);
                acc[kk][1] = pk2(svv, svv);
            }
            const float* wrow0 = w_s + (hf * 64 + ko * 2) * 66;
#pragma unroll 8
            for (int l = 0; l < 64; l += 2) {
                ulonglong2 p0 = *(const ulonglong2*)(bs + l * 32 + q * 4);
                ulonglong2 p1 = *(const ulonglong2*)(bs + (l + 1) * 32 + q * 4);
#pragma unroll
                for (int kk = 0; kk < 2; kk++) {
                    float2 w2 = *(const float2*)(wrow0 + kk * 66 + l);
                    unsigned long long wa = pk2(w2.x, w2.x);
                    unsigned long long wb = pk2(w2.y, w2.y);
                    fma2(acc[kk][0], p0.x, wa); fma2(acc[kk][1], p0.y, wa);
                    fma2(acc[kk][0], p1.x, wb); fma2(acc[kk][1], p1.y, wb);
                }
            }
#pragma unroll
            for (int kk = 0; kk < 2; kk++) {
                ulonglong2 o; o.x = acc[kk][0]; o.y = acc[kk][1];
                *(ulonglong2*)(lg + (ko * 2 + kk) * 36 + q * 4) = o;
            }
            __syncthreads();

            // ---- phase c: (b=cb, l_slot=ls), i = iq*8..iq*8+7, no max ----
            {
                float lv[8];
                float s8 = 0.f;
#pragma unroll
                for (int i = 0; i < 8; i++) {
                    lv[i] = __expf(lg[(ls * 32 + iq * 8 + i) * 36 + cb]);
                    s8 += lv[i];
                }
                pm[t] = s8;
                __syncthreads();           // also orders lg reads before next b
                float Z = pm[tb] + pm[tb + 64] + pm[tb + 128] + pm[tb + 192];
                int l = kq * 16 + ch * 4 + hf * 2 + ls;
                float s = bs[l * 32 + cb] / Z;
#pragma unroll
                for (int i = 0; i < 8; i++) accI[i] += lv[i] * s;
            }
        }
    }
    __syncthreads();

    // reduce the 2 l_slot partials per b (red2 aliases w_s; rows pad 33)
    float* red2 = w_s;
#pragma unroll
    for (int i = 0; i < 8; i++)
        red2[(ls * 32 + cb) * 33 + iq * 8 + i] = accI[i];
    __syncthreads();
#pragma unroll
    for (int r = 0; r < 4; r++) {
        int e = t * 4 + r;               // 0..1023
        int bb = e >> 5, i = e & 31;
        float s = red2[bb * 33 + i] + red2[(32 + bb) * 33 + i];
        g_cvp[(((size_t)kq * NJ + j) * NB + b0 + bb) * 32 + i] = s;
    }
}

// =============================================================================
// Kernel C: cv_total = body + 32 slot partials; out = conf * (cv@W^T + b)
// grid = 128 CTAs x 128 threads, 4 b per CTA (head_w staged once per CTA).
// =============================================================================
extern "C" __global__ void __launch_bounds__(128)
kC(const float* __restrict__ head_w, const float* __restrict__ head_b,
   float* __restrict__ out)
{
    __shared__ float hw[NO * 33];
    __shared__ float cvt[4 * 32];
    __shared__ float cf[4];
    const int t  = threadIdx.x;
    const int b0 = blockIdx.x * 4;

#pragma unroll
    for (int r = 0; r < 32; r++) {
        int e = t + 128 * r;             // 0..4095
        int o = e >> 5, i = e & 31;
        hw[o * 33 + i] = head_w[e];
    }
    {
        int bl = t >> 5, i = t & 31;
        int b = b0 + bl;
        float v = g_cv[b * 32 + i];
#pragma unroll
        for (int p = 0; p < 32; p++)
            v += g_cvp[((size_t)p * NB + b) * 32 + i];
        cvt[bl * 32 + i] = v;
    }
    if (t < 4) cf[t] = g_conf[b0 + t];
    __syncthreads();

    float hb = head_b[t];
#pragma unroll
    for (int bl = 0; bl < 4; bl++) {
        float d = hb;
#pragma unroll
        for (int i = 0; i < 32; i++) d += cvt[bl * 32 + i] * hw[t * 33 + i];
        out[(b0 + bl) * NO + t] = cf[bl] * d;
    }
}

// =============================================================================
extern "C" void kernel_launch(void* const* d_in, const int* in_sizes, int n_in,
                              void* d_out, int out_size)
{
    const float* wm  = (const float*)d_in[0];
    const float* cst = (const float*)d_in[1];
    const float* gam = (const float*)d_in[2];
    const float* bw  = (const float*)d_in[3];
    const float* bb  = (const float*)d_in[4];
    const float* sw  = (const float*)d_in[5];
    const float* sb  = (const float*)d_in[6];
    const float* hwp = (const float*)d_in[7];
    const float* hbp = (const float*)d_in[8];
    float* out = (float*)d_out;

    cudaFuncSetAttribute(kA1, cudaFuncAttributeMaxDynamicSharedMemorySize,
                         A_SMEM_FLOATS * 4);
    cudaFuncSetAttribute(kB, cudaFuncAttributeMaxDynamicSharedMemorySize,
                         B_SMEM_FLOATS * 4);

    dim3 ga(NB, NSPLIT);
    kA1<<<ga, 128, A_SMEM_FLOATS * 4>>>(wm, cst, gam);
    kA2<<<NB, 128>>>(gam, bw, bb);
    dim3 gb(16, 8, 4);
    kB<<<gb, 256, B_SMEM_FLOATS * 4>>>(sw, sb);
    kC<<<128, 128>>>(hwp, hbp, out);
}